// round 15
// baseline (speedup 1.0000x reference)
#include <cuda_runtime.h>
#include <cuda_fp16.h>
#include <cstdint>

// Problem constants
#define BB 2
#define TT 2048
#define CC 2048
#define NH 16
#define NKV 4
#define GRP 4
#define HS 128
#define WIN 1024
#define SNK 4

// Scratch (device globals; allocation APIs are forbidden)
__device__ __half g_ah[(size_t)BB * TT * CC];               // x rounded, then y rounded
__device__ __half g_bh[(size_t)(CC + 2 * NKV * HS) * CC];   // Wq|Wk|Wv 3072 x 2048
__device__ __half g_bo[(size_t)CC * CC];                    // Wo rounded
__device__ __half g_qh[(size_t)BB * TT * CC];
__device__ __half g_kh[(size_t)BB * TT * NKV * HS];
__device__ __half g_vh[(size_t)BB * TT * NKV * HS];

// ---------------------------------------------------------------------------
// Helpers
// ---------------------------------------------------------------------------
__device__ __forceinline__ uint32_t smem_u32(const void* p) {
    uint32_t a;
    asm("{ .reg .u64 t; cvta.to.shared.u64 t, %1; cvt.u32.u64 %0, t; }"
        : "=r"(a) : "l"(p));
    return a;
}

#define CP_ASYNC16(dst, src) \
    asm volatile("cp.async.cg.shared.global [%0], [%1], 16;" :: "r"(dst), "l"(src))
#define CP_ASYNC_COMMIT() asm volatile("cp.async.commit_group;" ::: "memory")
#define CP_ASYNC_WAIT1()  asm volatile("cp.async.wait_group 1;" ::: "memory")
#define CP_ASYNC_WAIT2()  asm volatile("cp.async.wait_group 2;" ::: "memory")

__device__ __forceinline__ void ldsm4(uint32_t* r, uint32_t addr) {
    asm volatile("ldmatrix.sync.aligned.m8n8.x4.shared.b16 {%0,%1,%2,%3}, [%4];"
                 : "=r"(r[0]), "=r"(r[1]), "=r"(r[2]), "=r"(r[3]) : "r"(addr));
}

__device__ __forceinline__ void ldsm4t(uint32_t* r, uint32_t addr) {
    asm volatile("ldmatrix.sync.aligned.m8n8.x4.trans.shared.b16 {%0,%1,%2,%3}, [%4];"
                 : "=r"(r[0]), "=r"(r[1]), "=r"(r[2]), "=r"(r[3]) : "r"(addr));
}

__device__ __forceinline__ void mma16816(float* d, const uint32_t* a,
                                         uint32_t b0, uint32_t b1) {
    asm volatile(
        "mma.sync.aligned.m16n8k16.row.col.f32.f16.f16.f32 "
        "{%0,%1,%2,%3}, {%4,%5,%6,%7}, {%8,%9}, {%0,%1,%2,%3};"
        : "+f"(d[0]), "+f"(d[1]), "+f"(d[2]), "+f"(d[3])
        : "r"(a[0]), "r"(a[1]), "r"(a[2]), "r"(a[3]), "r"(b0), "r"(b1));
}

__device__ __forceinline__ float ex2f(float x) {
    float y;
    asm("ex2.approx.f32 %0, %1;" : "=f"(y) : "f"(x));
    return y;
}

// ---------------------------------------------------------------------------
// Fused prep with MLP=4: round x -> g_ah, Wq|Wk|Wv -> g_bh, Wo -> g_bo
// ---------------------------------------------------------------------------
#define N4_X   (BB * TT * CC / 4)                 // 2097152
#define N4_WQ  (CC * CC / 4)                      // 1048576
#define N4_WKV (NKV * HS * CC / 4)                // 262144
#define N4_QKV (N4_WQ + 2 * N4_WKV)               // 1572864
#define N4_ALL (N4_X + N4_QKV + N4_WQ)            // 4718592

__global__ void __launch_bounds__(256) prep_all(
    const float* __restrict__ x,
    const float* __restrict__ Wq, const float* __restrict__ Wk,
    const float* __restrict__ Wv, const float* __restrict__ Wo,
    __half* __restrict__ ah, __half* __restrict__ bh, __half* __restrict__ bo)
{
    const int base = blockIdx.x * 1024 + threadIdx.x;

    float4 v[4];
    __half* dsts[4];
    int js[4];
    bool ok[4];
#pragma unroll
    for (int u = 0; u < 4; ++u) {
        int i = base + u * 256;
        ok[u] = (i < N4_ALL);
        if (ok[u]) {
            const float* src;
            int j;
            __half* dst;
            if (i < N4_X) {
                src = x; dst = ah; j = i;
            } else if (i < N4_X + N4_WQ) {
                src = Wq; dst = bh; j = i - N4_X;
            } else if (i < N4_X + N4_WQ + N4_WKV) {
                src = Wk; dst = bh + (size_t)4 * N4_WQ; j = i - N4_X - N4_WQ;
            } else if (i < N4_X + N4_QKV) {
                src = Wv; dst = bh + (size_t)4 * (N4_WQ + N4_WKV);
                j = i - N4_X - N4_WQ - N4_WKV;
            } else {
                src = Wo; dst = bo; j = i - N4_X - N4_QKV;
            }
            v[u] = ((const float4*)src)[j];
            dsts[u] = dst;
            js[u] = j;
        }
    }
#pragma unroll
    for (int u = 0; u < 4; ++u) {
        if (ok[u]) {
            __half2 h0 = __float22half2_rn(make_float2(v[u].x, v[u].y));
            __half2 h1 = __float22half2_rn(make_float2(v[u].z, v[u].w));
            uint32_t* op = (uint32_t*)(dsts[u] + (size_t)js[u] * 4);
            op[0] = *(uint32_t*)&h0;
            op[1] = *(uint32_t*)&h1;
        }
    }
}

// ---------------------------------------------------------------------------
// Single-product fp16 GEMM mainloop (C = Ah @ Bh^T, fp32 acc)
// CTA tile 128x128, BK=32, 8 warps (4x2), warp tile 32x64, 4-stage cp.async.
// ---------------------------------------------------------------------------
#define GBK 32
#define ROWB 80u
#define TILE_B (128u * ROWB)          // 10240
#define STG_B (2u * TILE_B)           // 20480 (A, B)
#define GSTAGES 4
#define GEMM_DYN_SMEM (GSTAGES * STG_B)   // 81920

#define GEMM_MAINLOOP(AH, BH, KDIM)                                              \
    const int tid = threadIdx.x;                                                 \
    const int wid = tid >> 5;                                                    \
    const int lane = tid & 31;                                                   \
    const int wr = wid >> 1;                                                     \
    const int wc = wid & 1;                                                      \
    const int niter = (KDIM) / GBK;                                              \
    const int lrow = tid >> 2;                                                   \
    const int lc = tid & 3;                                                      \
    auto load_stage = [&](int s, int kc) {                                       \
        uint32_t st = sbase + (uint32_t)s * STG_B;                               \
        size_t kof = (size_t)kc * GBK + lc * 8;                                  \
        const __half* aH = (AH) + (size_t)(m0 + lrow) * (KDIM) + kof;            \
        const __half* bH = (BH) + (size_t)(n0 + lrow) * (KDIM) + kof;            \
        uint32_t d = st + (uint32_t)lrow * ROWB + (uint32_t)lc * 16;             \
        CP_ASYNC16(d + 0u * TILE_B, aH);                                         \
        CP_ASYNC16(d + 1u * TILE_B, bH);                                         \
        uint32_t d2 = d + 64u * ROWB;                                            \
        size_t g2 = (size_t)64 * (KDIM);                                         \
        CP_ASYNC16(d2 + 0u * TILE_B, aH + g2);                                   \
        CP_ASYNC16(d2 + 1u * TILE_B, bH + g2);                                   \
    };                                                                           \
    float acc[2][8][4];                                                          \
    _Pragma("unroll")                                                            \
    for (int f = 0; f < 2; ++f)                                                  \
        _Pragma("unroll")                                                        \
        for (int j = 0; j < 8; ++j)                                              \
            _Pragma("unroll")                                                    \
            for (int e = 0; e < 4; ++e) acc[f][j][e] = 0.0f;                     \
    load_stage(0, 0);                                                            \
    CP_ASYNC_COMMIT();                                                           \
    load_stage(1, 1);                                                            \
    CP_ASYNC_COMMIT();                                                           \
    load_stage(2, 2);                                                            \
    CP_ASYNC_COMMIT();                                                           \
    const int fr = lane & 15;                                                    \
    const int fh = lane >> 4;                                                    \
    for (int i = 0; i < niter; ++i) {                                            \
        const int s = i % GSTAGES;                                               \
        CP_ASYNC_WAIT2();                                                        \
        __syncthreads();                                                         \
        if (i + 3 < niter) load_stage((i + 3) % GSTAGES, i + 3);                 \
        CP_ASYNC_COMMIT();                                                       \
        const uint32_t stA = sbase + (uint32_t)s * STG_B;                        \
        const uint32_t stB = stA + 1u * TILE_B;                                  \
        _Pragma("unroll")                                                        \
        for (int ks = 0; ks < 2; ++ks) {                                         \
            const uint32_t chunk = (uint32_t)((ks << 1) + fh) * 16u;             \
            uint32_t ah[2][4];                                                   \
            _Pragma("unroll")                                                    \
            for (int f = 0; f < 2; ++f) {                                        \
                uint32_t ad = stA + (uint32_t)(wr * 32 + f * 16 + fr) * ROWB + chunk; \
                ldsm4(ah[f], ad);                                                \
            }                                                                    \
            _Pragma("unroll")                                                    \
            for (int j4 = 0; j4 < 4; ++j4) {                                     \
                uint32_t bd = stB + (uint32_t)(wc * 64 + j4 * 16 + fr) * ROWB + chunk; \
                uint32_t bh4[4];                                                 \
                ldsm4(bh4, bd);                                                  \
                _Pragma("unroll")                                                \
                for (int f = 0; f < 2; ++f) {                                    \
                    mma16816(acc[f][2 * j4 + 0], ah[f], bh4[0], bh4[2]);         \
                    mma16816(acc[f][2 * j4 + 1], ah[f], bh4[1], bh4[3]);         \
                }                                                                \
            }                                                                    \
        }                                                                        \
    }

// Fused QKV projection GEMM: N = 3072 (Q 0-2047, K 2048-2559, V 2560-3071), fp16 out.
// Q is pre-scaled by softmax_scale * log2(e) so attention works in exp2 domain.
__global__ void __launch_bounds__(256, 2) gemm_qkv(
    const __half* __restrict__ Ah, const __half* __restrict__ Bh,
    __half* __restrict__ Qh, __half* __restrict__ Kh, __half* __restrict__ Vh)
{
    extern __shared__ char dsmem[];
    const uint32_t sbase = smem_u32(dsmem);
    const int m0 = blockIdx.y * 128;
    const int n0 = blockIdx.x * 128;

    GEMM_MAINLOOP(Ah, Bh, CC)

    const int er = lane >> 2;
    const int ec = (lane & 3) * 2;
    const float QSCL = 0.12751721769316523f;  // (1/sqrt(128)) * log2(e)
    __half* dst;
    int cb, stride;
    float oscl;
    if (n0 < CC)                 { dst = Qh; cb = 0;             stride = CC;      oscl = QSCL; }
    else if (n0 < CC + NKV * HS) { dst = Kh; cb = CC;            stride = NKV * HS; oscl = 1.0f; }
    else                         { dst = Vh; cb = CC + NKV * HS; stride = NKV * HS; oscl = 1.0f; }
#pragma unroll
    for (int f = 0; f < 2; ++f) {
        const int row = m0 + wr * 32 + f * 16 + er;
#pragma unroll
        for (int j = 0; j < 8; ++j) {
            const int col = n0 - cb + wc * 64 + j * 8 + ec;
            __half2 h0 = __float22half2_rn(
                make_float2(acc[f][j][0] * oscl, acc[f][j][1] * oscl));
            __half2 h1 = __float22half2_rn(
                make_float2(acc[f][j][2] * oscl, acc[f][j][3] * oscl));
            *(uint32_t*)&dst[(size_t)row * stride + col] = *(uint32_t*)&h0;
            *(uint32_t*)&dst[(size_t)(row + 8) * stride + col] = *(uint32_t*)&h1;
        }
    }
}

// Output projection GEMM: fp32 out, N = 2048
__global__ void __launch_bounds__(256, 2) gemm_out(
    const __half* __restrict__ Ah, const __half* __restrict__ Bh,
    float* __restrict__ C)
{
    extern __shared__ char dsmem[];
    const uint32_t sbase = smem_u32(dsmem);
    const int m0 = blockIdx.y * 128;
    const int n0 = blockIdx.x * 128;

    GEMM_MAINLOOP(Ah, Bh, CC)

    const int er = lane >> 2;
    const int ec = (lane & 3) * 2;
#pragma unroll
    for (int f = 0; f < 2; ++f) {
        const int row = m0 + wr * 32 + f * 16 + er;
#pragma unroll
        for (int j = 0; j < 8; ++j) {
            const int col = n0 + wc * 64 + j * 8 + ec;
            float2 v0 = {acc[f][j][0], acc[f][j][1]};
            float2 v1 = {acc[f][j][2], acc[f][j][3]};
            *(float2*)&C[(size_t)row * CC + col] = v0;
            *(float2*)&C[(size_t)(row + 8) * CC + col] = v1;
        }
    }
}

// ---------------------------------------------------------------------------
// FA2-style GQA attention, fp16 single-product, exp2-domain softmax, fp32 PV
// accumulators. Double-buffered KV, 2 CTAs/SM. Heavy q-tiles scheduled first.
// Per-warp 16-key-group visibility skipping (window + diagonal + sink).
// ---------------------------------------------------------------------------
#define AROW 272u
#define KV_OFF  (128u * AROW)          // 34816 (Q single copy)
#define KCOMP   17408u                 // 64*272
#define KV_STG  (2u * KCOMP)           // K + V
#define ATTN2_SMEM (KV_OFF + 2u * KV_STG)  // 104448

__global__ void __launch_bounds__(256, 2) attn_mma(
    const __half* __restrict__ qh, const __half* __restrict__ kh,
    const __half* __restrict__ vh, __half* __restrict__ yh)
{
    extern __shared__ char sm[];
    const uint32_t sb = smem_u32(sm);

    const int b = blockIdx.z;
    const int h = blockIdx.y;
    const int qb = gridDim.x - 1 - blockIdx.x;   // heavy tiles first
    const int q0 = qb * 128;
    const int kvh = h / GRP;

    const int tid = threadIdx.x;
    const int wid = tid >> 5;
    const int lane = tid & 31;
    const int fr = lane & 15;
    const int fh = lane >> 4;

    // Q load (single fp16, pre-scaled), resident
    {
        size_t qbase = ((size_t)(b * TT + q0) * NH + h) * HS;
#pragma unroll
        for (int c = 0; c < 8; ++c) {
            int idx = tid + c * 256;
            int r = idx >> 4;
            int ch = idx & 15;
            uint32_t dst = sb + (uint32_t)r * AROW + (uint32_t)ch * 16;
            CP_ASYNC16(dst, qh + qbase + (size_t)r * (NH * HS) + ch * 8);
        }
    }
    CP_ASYNC_COMMIT();

    // small=true loads only rows 0-15 of K and V (sink tile)
    auto load_kv = [&](int buf, int k0t, bool small) {
        uint32_t st = sb + KV_OFF + (uint32_t)buf * KV_STG;
        size_t kbase = ((size_t)(b * TT + k0t) * NKV + kvh) * HS;
        const int cmax = small ? 1 : 4;
#pragma unroll
        for (int c = 0; c < 4; ++c) {
            if (c < cmax) {
                int idx = tid + c * 256;
                int r = idx >> 4;
                int ch = idx & 15;
                size_t g = kbase + (size_t)r * (NKV * HS) + ch * 8;
                uint32_t d = st + (uint32_t)r * AROW + (uint32_t)ch * 16;
                CP_ASYNC16(d + 0u * KCOMP, kh + g);
                CP_ASYNC16(d + 1u * KCOMP, vh + g);
            }
        }
    };

    int lo = q0 - (WIN - 1);
    int kb_start = (lo > 0) ? (lo >> 6) : 0;
    int kb_end = (q0 + 127) >> 6;
    bool do_sink = (kb_start > 0);
    int ntiles = (kb_end - kb_start + 1) + (do_sink ? 1 : 0);
    auto kb_of = [&](int t) {
        return do_sink ? (t == 0 ? 0 : kb_start + t - 1) : (kb_start + t);
    };

    load_kv(0, kb_of(0) * 64, do_sink);
    CP_ASYNC_COMMIT();
    if (ntiles > 1) load_kv(1, kb_of(1) * 64, false);
    CP_ASYNC_COMMIT();

    float O[16][4];
#pragma unroll
    for (int n = 0; n < 16; ++n)
#pragma unroll
        for (int e = 0; e < 4; ++e) O[n][e] = 0.0f;
    float m0s = -1e30f, m1s = -1e30f;
    float l0s = 0.0f, l1s = 0.0f;

    const int r4 = lane >> 2;
    const int c2 = (lane & 3) * 2;
    const int qi_min = q0 + wid * 16;       // smallest query row in this warp
    const int qi_max = qi_min + 15;         // largest

    for (int t = 0; t < ntiles; ++t) {
        const int k0 = kb_of(t) * 64;
        const bool sink_small = do_sink && (t == 0);
        CP_ASYNC_WAIT1();
        __syncthreads();

        const uint32_t stg = sb + KV_OFF + (uint32_t)(t & 1) * KV_STG;

        // Per-warp visibility of each 16-key group:
        //   visible iff (col_min <= qi_max) && (col_max >= qi_min-(WIN-1) || col_min < SNK)
        int vis = 0;
        if (sink_small) {
            vis = 1;  // only group 0 (keys 0-15 loaded; SNK=4)
        } else {
#pragma unroll
            for (int kg = 0; kg < 4; ++kg) {
                int cmin = k0 + kg * 16;
                int cmax = cmin + 15;
                bool v = (cmin <= qi_max) &&
                         ((cmax >= qi_min - (WIN - 1)) || (cmin < SNK));
                vis |= (int)v << kg;
            }
        }

        // S = Q K^T (log2 units), only visible groups
        float S[8][4];
#pragma unroll
        for (int j = 0; j < 8; ++j)
#pragma unroll
            for (int e = 0; e < 4; ++e) S[j][e] = 0.0f;

#pragma unroll
        for (int kc = 0; kc < 8; ++kc) {
            uint32_t qaddr = sb + (uint32_t)(wid * 16 + fr) * AROW
                           + (uint32_t)kc * 32 + (uint32_t)fh * 16;
            uint32_t ah[4];
            ldsm4(ah, qaddr);
#pragma unroll
            for (int kg = 0; kg < 4; ++kg) {
                if ((vis >> kg) & 1) {
                    uint32_t kaddr = stg + (uint32_t)(kg * 16 + fr) * AROW
                                   + (uint32_t)kc * 32 + (uint32_t)fh * 16;
                    uint32_t bh4[4];
                    ldsm4(bh4, kaddr);
                    mma16816(S[2 * kg + 0], ah, bh4[0], bh4[2]);
                    mma16816(S[2 * kg + 1], ah, bh4[1], bh4[3]);
                }
            }
        }

        bool full = (k0 + 63 <= q0) && (k0 >= q0 + 127 - (WIN - 1));
        int qi0 = q0 + wid * 16 + r4;
        int qi1 = qi0 + 8;
        if (sink_small) {
#pragma unroll
            for (int j = 0; j < 8; ++j) {
                int kj = 8 * j + c2;
                bool v0 = (j < 2) && (kj + 0 < SNK);
                bool v1 = (j < 2) && (kj + 1 < SNK);
                if (!v0) { S[j][0] = -1e30f; S[j][2] = -1e30f; }
                if (!v1) { S[j][1] = -1e30f; S[j][3] = -1e30f; }
            }
        } else if (!full) {
#pragma unroll
            for (int j = 0; j < 8; ++j) {
                int kj = k0 + 8 * j + c2;
#pragma unroll
                for (int e = 0; e < 2; ++e) {
                    int col = kj + e;
                    bool v0 = (col <= qi0) && ((col >= qi0 - (WIN - 1)) || (col < SNK));
                    bool v1 = (col <= qi1) && ((col >= qi1 - (WIN - 1)) || (col < SNK));
                    if (!v0) S[j][e] = -1e30f;
                    if (!v1) S[j][2 + e] = -1e30f;
                }
            }
        }

        // Online softmax in exp2 domain
        float mx0 = -1e30f, mx1 = -1e30f;
#pragma unroll
        for (int j = 0; j < 8; ++j) {
            mx0 = fmaxf(mx0, fmaxf(S[j][0], S[j][1]));
            mx1 = fmaxf(mx1, fmaxf(S[j][2], S[j][3]));
        }
        mx0 = fmaxf(mx0, __shfl_xor_sync(0xFFFFFFFFu, mx0, 1));
        mx0 = fmaxf(mx0, __shfl_xor_sync(0xFFFFFFFFu, mx0, 2));
        mx1 = fmaxf(mx1, __shfl_xor_sync(0xFFFFFFFFu, mx1, 1));
        mx1 = fmaxf(mx1, __shfl_xor_sync(0xFFFFFFFFu, mx1, 2));

        float mn0 = fmaxf(m0s, mx0);
        float mn1 = fmaxf(m1s, mx1);
        float a0 = ex2f(m0s - mn0);
        float a1 = ex2f(m1s - mn1);
        m0s = mn0; m1s = mn1;

        float sum0 = 0.0f, sum1 = 0.0f;
#pragma unroll
        for (int j = 0; j < 8; ++j) {
            S[j][0] = ex2f(S[j][0] - mn0);
            S[j][1] = ex2f(S[j][1] - mn0);
            S[j][2] = ex2f(S[j][2] - mn1);
            S[j][3] = ex2f(S[j][3] - mn1);
            sum0 += S[j][0] + S[j][1];
            sum1 += S[j][2] + S[j][3];
        }
        sum0 += __shfl_xor_sync(0xFFFFFFFFu, sum0, 1);
        sum0 += __shfl_xor_sync(0xFFFFFFFFu, sum0, 2);
        sum1 += __shfl_xor_sync(0xFFFFFFFFu, sum1, 1);
        sum1 += __shfl_xor_sync(0xFFFFFFFFu, sum1, 2);
        l0s = l0s * a0 + sum0;
        l1s = l1s * a1 + sum1;

#pragma unroll
        for (int n = 0; n < 16; ++n) {
            O[n][0] *= a0; O[n][1] *= a0;
            O[n][2] *= a1; O[n][3] *= a1;
        }

        // Pack P to fp16 (only visible groups; invisible P == 0)
        uint32_t pH[4][4];
#pragma unroll
        for (int j2 = 0; j2 < 4; ++j2) {
            if ((vis >> j2) & 1) {
                const int t0 = 2 * j2, t1 = t0 + 1;
                __half2 g0 = __float22half2_rn(make_float2(S[t0][0], S[t0][1]));
                __half2 g1 = __float22half2_rn(make_float2(S[t0][2], S[t0][3]));
                __half2 g2 = __float22half2_rn(make_float2(S[t1][0], S[t1][1]));
                __half2 g3 = __float22half2_rn(make_float2(S[t1][2], S[t1][3]));
                pH[j2][0] = *(uint32_t*)&g0;
                pH[j2][1] = *(uint32_t*)&g1;
                pH[j2][2] = *(uint32_t*)&g2;
                pH[j2][3] = *(uint32_t*)&g3;
            }
        }

        // O += P V (fp32 accumulate), only visible groups
        const uint32_t vbase = stg + KCOMP;
#pragma unroll
        for (int kc = 0; kc < 4; ++kc) {
            if ((vis >> kc) & 1) {
#pragma unroll
                for (int dt = 0; dt < 8; ++dt) {
                    uint32_t vaddr = vbase + (uint32_t)(kc * 16 + fr) * AROW
                                   + (uint32_t)dt * 32 + (uint32_t)fh * 16;
                    uint32_t v4h[4];
                    ldsm4t(v4h, vaddr);
                    mma16816(O[2 * dt + 0], pH[kc], v4h[0], v4h[1]);
                    mma16816(O[2 * dt + 1], pH[kc], v4h[2], v4h[3]);
                }
            }
        }

        __syncthreads();
        if (t + 2 < ntiles) load_kv(t & 1, kb_of(t + 2) * 64, false);
        CP_ASYNC_COMMIT();
    }

    // normalize + rounded fp16 output
    float inv0 = 1.0f / l0s;
    float inv1 = 1.0f / l1s;
    size_t row0 = ((size_t)(b * TT + q0 + wid * 16 + r4) * NH + h) * HS;
    size_t row1 = row0 + (size_t)8 * NH * HS;
#pragma unroll
    for (int n = 0; n < 16; ++n) {
        int d = n * 8 + c2;
        __half2 o0 = __float22half2_rn(make_float2(O[n][0] * inv0, O[n][1] * inv0));
        __half2 o1 = __float22half2_rn(make_float2(O[n][2] * inv1, O[n][3] * inv1));
        *(uint32_t*)&yh[row0 + d] = *(uint32_t*)&o0;
        *(uint32_t*)&yh[row1 + d] = *(uint32_t*)&o1;
    }
}

// ---------------------------------------------------------------------------
extern "C" void kernel_launch(void* const* d_in, const int* in_sizes, int n_in,
                              void* d_out, int out_size)
{
    const float* x  = (const float*)d_in[0];
    const float* Wq = (const float*)d_in[1];
    const float* Wk = (const float*)d_in[2];
    const float* Wv = (const float*)d_in[3];
    const float* Wo = (const float*)d_in[4];
    float* out = (float*)d_out;

    __half *ah, *bh, *bo, *qh, *kh, *vh;
    cudaGetSymbolAddress((void**)&ah, g_ah);
    cudaGetSymbolAddress((void**)&bh, g_bh);
    cudaGetSymbolAddress((void**)&bo, g_bo);
    cudaGetSymbolAddress((void**)&qh, g_qh);
    cudaGetSymbolAddress((void**)&kh, g_kh);
    cudaGetSymbolAddress((void**)&vh, g_vh);

    const int M = BB * TT;        // 4096
    const int NS = NKV * HS;      // 512
    const int NQKV = CC + 2 * NS; // 3072

    cudaFuncSetAttribute(gemm_qkv, cudaFuncAttributeMaxDynamicSharedMemorySize,
                         GEMM_DYN_SMEM);
    cudaFuncSetAttribute(gemm_out, cudaFuncAttributeMaxDynamicSharedMemorySize,
                         GEMM_DYN_SMEM);
    cudaFuncSetAttribute(attn_mma, cudaFuncAttributeMaxDynamicSharedMemorySize,
                         ATTN2_SMEM);

    // Fused prep (MLP=4): round everything in one launch
    prep_all<<<(N4_ALL + 1023) / 1024, 256>>>(x, Wq, Wk, Wv, Wo, ah, bh, bo);

    // Fused QKV projection (fp16 out; Q pre-scaled into exp2 domain)
    gemm_qkv<<<dim3(NQKV / 128, M / 128), 256, GEMM_DYN_SMEM>>>(
        ah, bh, qh, kh, vh);

    // Attention -> fp16 y into A buffer (x no longer needed)
    attn_mma<<<dim3(TT / 128, NH, BB), 256, ATTN2_SMEM>>>(qh, kh, vh, ah);

    // Output projection (fp32 out)
    gemm_out<<<dim3(CC / 128, M / 128), 256, GEMM_DYN_SMEM>>>(ah, bo, out);
}

// round 16
// speedup vs baseline: 1.1461x; 1.1461x over previous
#include <cuda_runtime.h>
#include <cuda_fp16.h>
#include <cstdint>

// Problem constants
#define BB 2
#define TT 2048
#define CC 2048
#define NH 16
#define NKV 4
#define GRP 4
#define HS 128
#define WIN 1024
#define SNK 4

// Scratch (device globals; allocation APIs are forbidden)
__device__ __half g_ah[(size_t)BB * TT * CC];               // x rounded, then y rounded
__device__ __half g_bh[(size_t)(CC + 2 * NKV * HS) * CC];   // Wq|Wk|Wv 3072 x 2048
__device__ __half g_bo[(size_t)CC * CC];                    // Wo rounded
__device__ __half g_qh[(size_t)BB * TT * CC];
__device__ __half g_kh[(size_t)BB * TT * NKV * HS];
__device__ __half g_vh[(size_t)BB * TT * NKV * HS];

// ---------------------------------------------------------------------------
// Helpers
// ---------------------------------------------------------------------------
__device__ __forceinline__ uint32_t smem_u32(const void* p) {
    uint32_t a;
    asm("{ .reg .u64 t; cvta.to.shared.u64 t, %1; cvt.u32.u64 %0, t; }"
        : "=r"(a) : "l"(p));
    return a;
}

#define CP_ASYNC16(dst, src) \
    asm volatile("cp.async.cg.shared.global [%0], [%1], 16;" :: "r"(dst), "l"(src))
#define CP_ASYNC_COMMIT() asm volatile("cp.async.commit_group;" ::: "memory")
#define CP_ASYNC_WAIT1()  asm volatile("cp.async.wait_group 1;" ::: "memory")
#define CP_ASYNC_WAIT2()  asm volatile("cp.async.wait_group 2;" ::: "memory")

__device__ __forceinline__ void ldsm4(uint32_t* r, uint32_t addr) {
    asm volatile("ldmatrix.sync.aligned.m8n8.x4.shared.b16 {%0,%1,%2,%3}, [%4];"
                 : "=r"(r[0]), "=r"(r[1]), "=r"(r[2]), "=r"(r[3]) : "r"(addr));
}

__device__ __forceinline__ void ldsm4t(uint32_t* r, uint32_t addr) {
    asm volatile("ldmatrix.sync.aligned.m8n8.x4.trans.shared.b16 {%0,%1,%2,%3}, [%4];"
                 : "=r"(r[0]), "=r"(r[1]), "=r"(r[2]), "=r"(r[3]) : "r"(addr));
}

__device__ __forceinline__ void mma16816(float* d, const uint32_t* a,
                                         uint32_t b0, uint32_t b1) {
    asm volatile(
        "mma.sync.aligned.m16n8k16.row.col.f32.f16.f16.f32 "
        "{%0,%1,%2,%3}, {%4,%5,%6,%7}, {%8,%9}, {%0,%1,%2,%3};"
        : "+f"(d[0]), "+f"(d[1]), "+f"(d[2]), "+f"(d[3])
        : "r"(a[0]), "r"(a[1]), "r"(a[2]), "r"(a[3]), "r"(b0), "r"(b1));
}

__device__ __forceinline__ float ex2f(float x) {
    float y;
    asm("ex2.approx.f32 %0, %1;" : "=f"(y) : "f"(x));
    return y;
}

// ---------------------------------------------------------------------------
// Fused prep with MLP=4: round x -> g_ah, Wq|Wk|Wv -> g_bh, Wo -> g_bo
// ---------------------------------------------------------------------------
#define N4_X   (BB * TT * CC / 4)                 // 2097152
#define N4_WQ  (CC * CC / 4)                      // 1048576
#define N4_WKV (NKV * HS * CC / 4)                // 262144
#define N4_QKV (N4_WQ + 2 * N4_WKV)               // 1572864
#define N4_ALL (N4_X + N4_QKV + N4_WQ)            // 4718592

__global__ void __launch_bounds__(256) prep_all(
    const float* __restrict__ x,
    const float* __restrict__ Wq, const float* __restrict__ Wk,
    const float* __restrict__ Wv, const float* __restrict__ Wo,
    __half* __restrict__ ah, __half* __restrict__ bh, __half* __restrict__ bo)
{
    const int base = blockIdx.x * 1024 + threadIdx.x;

    float4 v[4];
    __half* dsts[4];
    int js[4];
    bool ok[4];
#pragma unroll
    for (int u = 0; u < 4; ++u) {
        int i = base + u * 256;
        ok[u] = (i < N4_ALL);
        if (ok[u]) {
            const float* src;
            int j;
            __half* dst;
            if (i < N4_X) {
                src = x; dst = ah; j = i;
            } else if (i < N4_X + N4_WQ) {
                src = Wq; dst = bh; j = i - N4_X;
            } else if (i < N4_X + N4_WQ + N4_WKV) {
                src = Wk; dst = bh + (size_t)4 * N4_WQ; j = i - N4_X - N4_WQ;
            } else if (i < N4_X + N4_QKV) {
                src = Wv; dst = bh + (size_t)4 * (N4_WQ + N4_WKV);
                j = i - N4_X - N4_WQ - N4_WKV;
            } else {
                src = Wo; dst = bo; j = i - N4_X - N4_QKV;
            }
            v[u] = ((const float4*)src)[j];
            dsts[u] = dst;
            js[u] = j;
        }
    }
#pragma unroll
    for (int u = 0; u < 4; ++u) {
        if (ok[u]) {
            __half2 h0 = __float22half2_rn(make_float2(v[u].x, v[u].y));
            __half2 h1 = __float22half2_rn(make_float2(v[u].z, v[u].w));
            uint32_t* op = (uint32_t*)(dsts[u] + (size_t)js[u] * 4);
            op[0] = *(uint32_t*)&h0;
            op[1] = *(uint32_t*)&h1;
        }
    }
}

// ---------------------------------------------------------------------------
// Single-product fp16 GEMM mainloop (C = Ah @ Bh^T, fp32 acc)
// CTA tile 128x128, BK=32, 8 warps (4x2), warp tile 32x64, 4-stage cp.async.
// ---------------------------------------------------------------------------
#define GBK 32
#define ROWB 80u
#define TILE_B (128u * ROWB)          // 10240
#define STG_B (2u * TILE_B)           // 20480 (A, B)
#define GSTAGES 4
#define GEMM_DYN_SMEM (GSTAGES * STG_B)   // 81920

#define GEMM_MAINLOOP(AH, BH, KDIM)                                              \
    const int tid = threadIdx.x;                                                 \
    const int wid = tid >> 5;                                                    \
    const int lane = tid & 31;                                                   \
    const int wr = wid >> 1;                                                     \
    const int wc = wid & 1;                                                      \
    const int niter = (KDIM) / GBK;                                              \
    const int lrow = tid >> 2;                                                   \
    const int lc = tid & 3;                                                      \
    auto load_stage = [&](int s, int kc) {                                       \
        uint32_t st = sbase + (uint32_t)s * STG_B;                               \
        size_t kof = (size_t)kc * GBK + lc * 8;                                  \
        const __half* aH = (AH) + (size_t)(m0 + lrow) * (KDIM) + kof;            \
        const __half* bH = (BH) + (size_t)(n0 + lrow) * (KDIM) + kof;            \
        uint32_t d = st + (uint32_t)lrow * ROWB + (uint32_t)lc * 16;             \
        CP_ASYNC16(d + 0u * TILE_B, aH);                                         \
        CP_ASYNC16(d + 1u * TILE_B, bH);                                         \
        uint32_t d2 = d + 64u * ROWB;                                            \
        size_t g2 = (size_t)64 * (KDIM);                                         \
        CP_ASYNC16(d2 + 0u * TILE_B, aH + g2);                                   \
        CP_ASYNC16(d2 + 1u * TILE_B, bH + g2);                                   \
    };                                                                           \
    float acc[2][8][4];                                                          \
    _Pragma("unroll")                                                            \
    for (int f = 0; f < 2; ++f)                                                  \
        _Pragma("unroll")                                                        \
        for (int j = 0; j < 8; ++j)                                              \
            _Pragma("unroll")                                                    \
            for (int e = 0; e < 4; ++e) acc[f][j][e] = 0.0f;                     \
    load_stage(0, 0);                                                            \
    CP_ASYNC_COMMIT();                                                           \
    load_stage(1, 1);                                                            \
    CP_ASYNC_COMMIT();                                                           \
    load_stage(2, 2);                                                            \
    CP_ASYNC_COMMIT();                                                           \
    const int fr = lane & 15;                                                    \
    const int fh = lane >> 4;                                                    \
    for (int i = 0; i < niter; ++i) {                                            \
        const int s = i % GSTAGES;                                               \
        CP_ASYNC_WAIT2();                                                        \
        __syncthreads();                                                         \
        if (i + 3 < niter) load_stage((i + 3) % GSTAGES, i + 3);                 \
        CP_ASYNC_COMMIT();                                                       \
        const uint32_t stA = sbase + (uint32_t)s * STG_B;                        \
        const uint32_t stB = stA + 1u * TILE_B;                                  \
        _Pragma("unroll")                                                        \
        for (int ks = 0; ks < 2; ++ks) {                                         \
            const uint32_t chunk = (uint32_t)((ks << 1) + fh) * 16u;             \
            uint32_t ah[2][4];                                                   \
            _Pragma("unroll")                                                    \
            for (int f = 0; f < 2; ++f) {                                        \
                uint32_t ad = stA + (uint32_t)(wr * 32 + f * 16 + fr) * ROWB + chunk; \
                ldsm4(ah[f], ad);                                                \
            }                                                                    \
            _Pragma("unroll")                                                    \
            for (int j4 = 0; j4 < 4; ++j4) {                                     \
                uint32_t bd = stB + (uint32_t)(wc * 64 + j4 * 16 + fr) * ROWB + chunk; \
                uint32_t bh4[4];                                                 \
                ldsm4(bh4, bd);                                                  \
                _Pragma("unroll")                                                \
                for (int f = 0; f < 2; ++f) {                                    \
                    mma16816(acc[f][2 * j4 + 0], ah[f], bh4[0], bh4[2]);         \
                    mma16816(acc[f][2 * j4 + 1], ah[f], bh4[1], bh4[3]);         \
                }                                                                \
            }                                                                    \
        }                                                                        \
    }

// Fused QKV projection GEMM: N = 3072 (Q 0-2047, K 2048-2559, V 2560-3071), fp16 out.
// Q is pre-scaled by softmax_scale * log2(e) so attention works in exp2 domain.
__global__ void __launch_bounds__(256, 2) gemm_qkv(
    const __half* __restrict__ Ah, const __half* __restrict__ Bh,
    __half* __restrict__ Qh, __half* __restrict__ Kh, __half* __restrict__ Vh)
{
    extern __shared__ char dsmem[];
    const uint32_t sbase = smem_u32(dsmem);
    const int m0 = blockIdx.y * 128;
    const int n0 = blockIdx.x * 128;

    GEMM_MAINLOOP(Ah, Bh, CC)

    const int er = lane >> 2;
    const int ec = (lane & 3) * 2;
    const float QSCL = 0.12751721769316523f;  // (1/sqrt(128)) * log2(e)
    __half* dst;
    int cb, stride;
    float oscl;
    if (n0 < CC)                 { dst = Qh; cb = 0;             stride = CC;      oscl = QSCL; }
    else if (n0 < CC + NKV * HS) { dst = Kh; cb = CC;            stride = NKV * HS; oscl = 1.0f; }
    else                         { dst = Vh; cb = CC + NKV * HS; stride = NKV * HS; oscl = 1.0f; }
#pragma unroll
    for (int f = 0; f < 2; ++f) {
        const int row = m0 + wr * 32 + f * 16 + er;
#pragma unroll
        for (int j = 0; j < 8; ++j) {
            const int col = n0 - cb + wc * 64 + j * 8 + ec;
            __half2 h0 = __float22half2_rn(
                make_float2(acc[f][j][0] * oscl, acc[f][j][1] * oscl));
            __half2 h1 = __float22half2_rn(
                make_float2(acc[f][j][2] * oscl, acc[f][j][3] * oscl));
            *(uint32_t*)&dst[(size_t)row * stride + col] = *(uint32_t*)&h0;
            *(uint32_t*)&dst[(size_t)(row + 8) * stride + col] = *(uint32_t*)&h1;
        }
    }
}

// Output projection GEMM: fp32 out, N = 2048
__global__ void __launch_bounds__(256, 2) gemm_out(
    const __half* __restrict__ Ah, const __half* __restrict__ Bh,
    float* __restrict__ C)
{
    extern __shared__ char dsmem[];
    const uint32_t sbase = smem_u32(dsmem);
    const int m0 = blockIdx.y * 128;
    const int n0 = blockIdx.x * 128;

    GEMM_MAINLOOP(Ah, Bh, CC)

    const int er = lane >> 2;
    const int ec = (lane & 3) * 2;
#pragma unroll
    for (int f = 0; f < 2; ++f) {
        const int row = m0 + wr * 32 + f * 16 + er;
#pragma unroll
        for (int j = 0; j < 8; ++j) {
            const int col = n0 + wc * 64 + j * 8 + ec;
            float2 v0 = {acc[f][j][0], acc[f][j][1]};
            float2 v1 = {acc[f][j][2], acc[f][j][3]};
            *(float2*)&C[(size_t)row * CC + col] = v0;
            *(float2*)&C[(size_t)(row + 8) * CC + col] = v1;
        }
    }
}

// ---------------------------------------------------------------------------
// FA2-style GQA attention, fp16 single-product, exp2-domain softmax, fp32 PV
// accumulators. Double-buffered KV, 2 CTAs/SM. Heavy q-tiles scheduled first.
// Sink tile loads/computes only its first 16-key group. Whole-tile
// warp-uniform skip when a warp's 16 query rows see nothing in a tile.
// ---------------------------------------------------------------------------
#define AROW 272u
#define KV_OFF  (128u * AROW)          // 34816 (Q single copy)
#define KCOMP   17408u                 // 64*272
#define KV_STG  (2u * KCOMP)           // K + V
#define ATTN2_SMEM (KV_OFF + 2u * KV_STG)  // 104448

__global__ void __launch_bounds__(256, 2) attn_mma(
    const __half* __restrict__ qh, const __half* __restrict__ kh,
    const __half* __restrict__ vh, __half* __restrict__ yh)
{
    extern __shared__ char sm[];
    const uint32_t sb = smem_u32(sm);

    const int b = blockIdx.z;
    const int h = blockIdx.y;
    const int qb = gridDim.x - 1 - blockIdx.x;   // heavy tiles first
    const int q0 = qb * 128;
    const int kvh = h / GRP;

    const int tid = threadIdx.x;
    const int wid = tid >> 5;
    const int lane = tid & 31;
    const int fr = lane & 15;
    const int fh = lane >> 4;

    // Q load (single fp16, pre-scaled), resident
    {
        size_t qbase = ((size_t)(b * TT + q0) * NH + h) * HS;
#pragma unroll
        for (int c = 0; c < 8; ++c) {
            int idx = tid + c * 256;
            int r = idx >> 4;
            int ch = idx & 15;
            uint32_t dst = sb + (uint32_t)r * AROW + (uint32_t)ch * 16;
            CP_ASYNC16(dst, qh + qbase + (size_t)r * (NH * HS) + ch * 8);
        }
    }
    CP_ASYNC_COMMIT();

    // small=true loads only rows 0-15 of K and V (sink tile)
    auto load_kv = [&](int buf, int k0t, bool small) {
        uint32_t st = sb + KV_OFF + (uint32_t)buf * KV_STG;
        size_t kbase = ((size_t)(b * TT + k0t) * NKV + kvh) * HS;
        const int cmax = small ? 1 : 4;
#pragma unroll
        for (int c = 0; c < 4; ++c) {
            if (c < cmax) {
                int idx = tid + c * 256;
                int r = idx >> 4;
                int ch = idx & 15;
                size_t g = kbase + (size_t)r * (NKV * HS) + ch * 8;
                uint32_t d = st + (uint32_t)r * AROW + (uint32_t)ch * 16;
                CP_ASYNC16(d + 0u * KCOMP, kh + g);
                CP_ASYNC16(d + 1u * KCOMP, vh + g);
            }
        }
    };

    int lo = q0 - (WIN - 1);
    int kb_start = (lo > 0) ? (lo >> 6) : 0;
    int kb_end = (q0 + 127) >> 6;
    bool do_sink = (kb_start > 0);
    int ntiles = (kb_end - kb_start + 1) + (do_sink ? 1 : 0);
    auto kb_of = [&](int t) {
        return do_sink ? (t == 0 ? 0 : kb_start + t - 1) : (kb_start + t);
    };

    load_kv(0, kb_of(0) * 64, do_sink);
    CP_ASYNC_COMMIT();
    if (ntiles > 1) load_kv(1, kb_of(1) * 64, false);
    CP_ASYNC_COMMIT();

    float O[16][4];
#pragma unroll
    for (int n = 0; n < 16; ++n)
#pragma unroll
        for (int e = 0; e < 4; ++e) O[n][e] = 0.0f;
    float m0s = -1e30f, m1s = -1e30f;
    float l0s = 0.0f, l1s = 0.0f;

    const int r4 = lane >> 2;
    const int c2 = (lane & 3) * 2;
    const int qi_min = q0 + wid * 16;
    const int qi_max = qi_min + 15;

    for (int t = 0; t < ntiles; ++t) {
        const int k0 = kb_of(t) * 64;
        const bool sink_small = do_sink && (t == 0);
        CP_ASYNC_WAIT1();
        __syncthreads();

        // Warp-uniform whole-tile visibility: skip if all 16 of this warp's
        // query rows see nothing in this 64-key tile. (Skipped tile would
        // leave m/l/O unchanged: alpha=1, sums=0.)
        const bool tile_vis = sink_small ||
            !((k0 > qi_max) ||
              ((k0 + 63 < qi_min - (WIN - 1)) && (k0 >= SNK)));

        if (tile_vis) {
            const uint32_t stg = sb + KV_OFF + (uint32_t)(t & 1) * KV_STG;

            // S = Q K^T (log2 units: Q pre-scaled by scale*log2e)
            float S[8][4];
#pragma unroll
            for (int j = 0; j < 8; ++j)
#pragma unroll
                for (int e = 0; e < 4; ++e) S[j][e] = 0.0f;

            const int kgmax = sink_small ? 1 : 4;
#pragma unroll
            for (int kc = 0; kc < 8; ++kc) {
                uint32_t qaddr = sb + (uint32_t)(wid * 16 + fr) * AROW
                               + (uint32_t)kc * 32 + (uint32_t)fh * 16;
                uint32_t ah[4];
                ldsm4(ah, qaddr);
#pragma unroll
                for (int kg = 0; kg < 4; ++kg) {
                    if (kg < kgmax) {
                        uint32_t kaddr = stg + (uint32_t)(kg * 16 + fr) * AROW
                                       + (uint32_t)kc * 32 + (uint32_t)fh * 16;
                        uint32_t bh4[4];
                        ldsm4(bh4, kaddr);
                        mma16816(S[2 * kg + 0], ah, bh4[0], bh4[2]);
                        mma16816(S[2 * kg + 1], ah, bh4[1], bh4[3]);
                    }
                }
            }

            bool full = (k0 + 63 <= q0) && (k0 >= q0 + 127 - (WIN - 1));
            int qi0 = q0 + wid * 16 + r4;
            int qi1 = qi0 + 8;
            if (sink_small) {
#pragma unroll
                for (int j = 0; j < 8; ++j) {
                    int kj = 8 * j + c2;
                    bool v0 = (j < 2) && (kj + 0 < SNK);
                    bool v1 = (j < 2) && (kj + 1 < SNK);
                    if (!v0) { S[j][0] = -1e30f; S[j][2] = -1e30f; }
                    if (!v1) { S[j][1] = -1e30f; S[j][3] = -1e30f; }
                }
            } else if (!full) {
#pragma unroll
                for (int j = 0; j < 8; ++j) {
                    int kj = k0 + 8 * j + c2;
#pragma unroll
                    for (int e = 0; e < 2; ++e) {
                        int col = kj + e;
                        bool v0 = (col <= qi0) && ((col >= qi0 - (WIN - 1)) || (col < SNK));
                        bool v1 = (col <= qi1) && ((col >= qi1 - (WIN - 1)) || (col < SNK));
                        if (!v0) S[j][e] = -1e30f;
                        if (!v1) S[j][2 + e] = -1e30f;
                    }
                }
            }

            // Online softmax in exp2 domain
            float mx0 = -1e30f, mx1 = -1e30f;
#pragma unroll
            for (int j = 0; j < 8; ++j) {
                mx0 = fmaxf(mx0, fmaxf(S[j][0], S[j][1]));
                mx1 = fmaxf(mx1, fmaxf(S[j][2], S[j][3]));
            }
            mx0 = fmaxf(mx0, __shfl_xor_sync(0xFFFFFFFFu, mx0, 1));
            mx0 = fmaxf(mx0, __shfl_xor_sync(0xFFFFFFFFu, mx0, 2));
            mx1 = fmaxf(mx1, __shfl_xor_sync(0xFFFFFFFFu, mx1, 1));
            mx1 = fmaxf(mx1, __shfl_xor_sync(0xFFFFFFFFu, mx1, 2));

            float mn0 = fmaxf(m0s, mx0);
            float mn1 = fmaxf(m1s, mx1);
            float a0 = ex2f(m0s - mn0);
            float a1 = ex2f(m1s - mn1);
            m0s = mn0; m1s = mn1;

            float sum0 = 0.0f, sum1 = 0.0f;
#pragma unroll
            for (int j = 0; j < 8; ++j) {
                S[j][0] = ex2f(S[j][0] - mn0);
                S[j][1] = ex2f(S[j][1] - mn0);
                S[j][2] = ex2f(S[j][2] - mn1);
                S[j][3] = ex2f(S[j][3] - mn1);
                sum0 += S[j][0] + S[j][1];
                sum1 += S[j][2] + S[j][3];
            }
            sum0 += __shfl_xor_sync(0xFFFFFFFFu, sum0, 1);
            sum0 += __shfl_xor_sync(0xFFFFFFFFu, sum0, 2);
            sum1 += __shfl_xor_sync(0xFFFFFFFFu, sum1, 1);
            sum1 += __shfl_xor_sync(0xFFFFFFFFu, sum1, 2);
            l0s = l0s * a0 + sum0;
            l1s = l1s * a1 + sum1;

#pragma unroll
            for (int n = 0; n < 16; ++n) {
                O[n][0] *= a0; O[n][1] *= a0;
                O[n][2] *= a1; O[n][3] *= a1;
            }

            // Pack P to fp16
            uint32_t pH[4][4];
#pragma unroll
            for (int j2 = 0; j2 < 4; ++j2) {
                const int t0 = 2 * j2, t1 = t0 + 1;
                __half2 g0 = __float22half2_rn(make_float2(S[t0][0], S[t0][1]));
                __half2 g1 = __float22half2_rn(make_float2(S[t0][2], S[t0][3]));
                __half2 g2 = __float22half2_rn(make_float2(S[t1][0], S[t1][1]));
                __half2 g3 = __float22half2_rn(make_float2(S[t1][2], S[t1][3]));
                pH[j2][0] = *(uint32_t*)&g0;
                pH[j2][1] = *(uint32_t*)&g1;
                pH[j2][2] = *(uint32_t*)&g2;
                pH[j2][3] = *(uint32_t*)&g3;
            }

            // O += P V (fp32 accumulate)
            const uint32_t vbase = stg + KCOMP;
            const int kcmax = sink_small ? 1 : 4;
#pragma unroll
            for (int kc = 0; kc < 4; ++kc) {
                if (kc < kcmax) {
#pragma unroll
                    for (int dt = 0; dt < 8; ++dt) {
                        uint32_t vaddr = vbase + (uint32_t)(kc * 16 + fr) * AROW
                                       + (uint32_t)dt * 32 + (uint32_t)fh * 16;
                        uint32_t v4h[4];
                        ldsm4t(v4h, vaddr);
                        mma16816(O[2 * dt + 0], pH[kc], v4h[0], v4h[1]);
                        mma16816(O[2 * dt + 1], pH[kc], v4h[2], v4h[3]);
                    }
                }
            }
        }

        __syncthreads();
        if (t + 2 < ntiles) load_kv(t & 1, kb_of(t + 2) * 64, false);
        CP_ASYNC_COMMIT();
    }

    // normalize + rounded fp16 output
    float inv0 = 1.0f / l0s;
    float inv1 = 1.0f / l1s;
    size_t row0 = ((size_t)(b * TT + q0 + wid * 16 + r4) * NH + h) * HS;
    size_t row1 = row0 + (size_t)8 * NH * HS;
#pragma unroll
    for (int n = 0; n < 16; ++n) {
        int d = n * 8 + c2;
        __half2 o0 = __float22half2_rn(make_float2(O[n][0] * inv0, O[n][1] * inv0));
        __half2 o1 = __float22half2_rn(make_float2(O[n][2] * inv1, O[n][3] * inv1));
        *(uint32_t*)&yh[row0 + d] = *(uint32_t*)&o0;
        *(uint32_t*)&yh[row1 + d] = *(uint32_t*)&o1;
    }
}

// ---------------------------------------------------------------------------
extern "C" void kernel_launch(void* const* d_in, const int* in_sizes, int n_in,
                              void* d_out, int out_size)
{
    const float* x  = (const float*)d_in[0];
    const float* Wq = (const float*)d_in[1];
    const float* Wk = (const float*)d_in[2];
    const float* Wv = (const float*)d_in[3];
    const float* Wo = (const float*)d_in[4];
    float* out = (float*)d_out;

    __half *ah, *bh, *bo, *qh, *kh, *vh;
    cudaGetSymbolAddress((void**)&ah, g_ah);
    cudaGetSymbolAddress((void**)&bh, g_bh);
    cudaGetSymbolAddress((void**)&bo, g_bo);
    cudaGetSymbolAddress((void**)&qh, g_qh);
    cudaGetSymbolAddress((void**)&kh, g_kh);
    cudaGetSymbolAddress((void**)&vh, g_vh);

    const int M = BB * TT;        // 4096
    const int NS = NKV * HS;      // 512
    const int NQKV = CC + 2 * NS; // 3072

    cudaFuncSetAttribute(gemm_qkv, cudaFuncAttributeMaxDynamicSharedMemorySize,
                         GEMM_DYN_SMEM);
    cudaFuncSetAttribute(gemm_out, cudaFuncAttributeMaxDynamicSharedMemorySize,
                         GEMM_DYN_SMEM);
    cudaFuncSetAttribute(attn_mma, cudaFuncAttributeMaxDynamicSharedMemorySize,
                         ATTN2_SMEM);

    // Fused prep (MLP=4): round everything in one launch
    prep_all<<<(N4_ALL + 1023) / 1024, 256>>>(x, Wq, Wk, Wv, Wo, ah, bh, bo);

    // Fused QKV projection (fp16 out; Q pre-scaled into exp2 domain)
    gemm_qkv<<<dim3(NQKV / 128, M / 128), 256, GEMM_DYN_SMEM>>>(
        ah, bh, qh, kh, vh);

    // Attention -> fp16 y into A buffer (x no longer needed)
    attn_mma<<<dim3(TT / 128, NH, BB), 256, ATTN2_SMEM>>>(qh, kh, vh, ah);

    // Output projection (fp32 out)
    gemm_out<<<dim3(CC / 128, M / 128), 256, GEMM_DYN_SMEM>>>(ah, bo, out);
}